// round 1
// baseline (speedup 1.0000x reference)
#include <cuda_runtime.h>
#include <cuda_bf16.h>
#include <cstdint>

#define NN 10000
#define EE 320000
#define ET (EE + NN)
#define DIN 256

// ---------------- scratch (no allocations allowed) ----------------
__device__ float g_xl[NN * 256];
__device__ float g_xr[NN * 256];
__device__ float g_h0[NN * 256];
__device__ float g_h1[NN * 256];
__device__ float g_z [NN * 32];
__device__ int   g_deg[NN];
__device__ int   g_cur[NN];
__device__ int   g_off[NN + 1];
__device__ int   g_adj[ET];

// ---------------- CSR build ----------------
__global__ void zero_kernel(int* a, int* b, int n) {
    int i = blockIdx.x * blockDim.x + threadIdx.x;
    if (i < n) { a[i] = 0; b[i] = 0; }
}

__global__ void count_kernel(const int* __restrict__ ei, int* __restrict__ deg) {
    int t = blockIdx.x * blockDim.x + threadIdx.x;
    if (t >= ET) return;
    int d = (t < EE) ? ei[EE + t] : (t - EE);
    atomicAdd(&deg[d], 1);
}

__global__ void scan_kernel(const int* __restrict__ deg, int* __restrict__ off) {
    __shared__ int sums[1024];
    const int IPT = 10;  // 1024*10 >= NN+1
    int tid = threadIdx.x;
    int base = tid * IPT;
    int local[IPT];
    int s = 0;
#pragma unroll
    for (int i = 0; i < IPT; i++) {
        int idx = base + i;
        int v = (idx < NN) ? deg[idx] : 0;
        local[i] = s;
        s += v;
    }
    sums[tid] = s;
    __syncthreads();
    for (int o = 1; o < 1024; o <<= 1) {
        int v = (tid >= o) ? sums[tid - o] : 0;
        __syncthreads();
        sums[tid] += v;
        __syncthreads();
    }
    int pre = (tid == 0) ? 0 : sums[tid - 1];
#pragma unroll
    for (int i = 0; i < IPT; i++) {
        int idx = base + i;
        if (idx <= NN) off[idx] = pre + local[i];
    }
}

__global__ void scatter_kernel(const int* __restrict__ ei, const int* __restrict__ off,
                               int* __restrict__ cur, int* __restrict__ adj) {
    int t = blockIdx.x * blockDim.x + threadIdx.x;
    if (t >= ET) return;
    int s, d;
    if (t < EE) { s = ei[t]; d = ei[EE + t]; }
    else        { s = t - EE; d = s; }
    int pos = off[d] + atomicAdd(&cur[d], 1);
    adj[pos] = s;
}

// per-node insertion sort -> deterministic accumulation order
__global__ void sort_kernel(const int* __restrict__ off, int* __restrict__ adj) {
    int i = blockIdx.x * blockDim.x + threadIdx.x;
    if (i >= NN) return;
    int b = off[i], e = off[i + 1];
    for (int p = b + 1; p < e; p++) {
        int v = adj[p];
        int q = p - 1;
        while (q >= b && adj[q] > v) { adj[q + 1] = adj[q]; q--; }
        adj[q + 1] = v;
    }
}

// ---------------- tiled SIMT GEMM: C[M,Nc] = A[M,K] @ B[K,Nc] + bias ----------------
__global__ void gemm_bias_kernel(const float* __restrict__ A, const float* __restrict__ B,
                                 const float* __restrict__ bias, float* __restrict__ C,
                                 int M, int K, int Nc) {
    __shared__ float As[64][33];
    __shared__ float Bs[32][64];
    int tid = threadIdx.x;
    int tx = tid & 15, ty = tid >> 4;
    int i0 = blockIdx.y * 64, j0 = blockIdx.x * 64;
    float acc[4][4] = {};
    for (int k0 = 0; k0 < K; k0 += 32) {
#pragma unroll
        for (int l = 0; l < 8; l++) {
            int lin = tid + l * 256;
            int m = lin >> 5, k = lin & 31;
            int gm = i0 + m;
            As[m][k] = (gm < M) ? A[(size_t)gm * K + k0 + k] : 0.f;
        }
#pragma unroll
        for (int l = 0; l < 8; l++) {
            int lin = tid + l * 256;
            int k = lin >> 6, n = lin & 63;
            int gn = j0 + n;
            Bs[k][n] = (gn < Nc) ? B[(size_t)(k0 + k) * Nc + gn] : 0.f;
        }
        __syncthreads();
#pragma unroll
        for (int k = 0; k < 32; k++) {
            float a[4];
#pragma unroll
            for (int i = 0; i < 4; i++) a[i] = As[ty * 4 + i][k];
            float4 bv = *(const float4*)&Bs[k][tx * 4];
            float b[4] = {bv.x, bv.y, bv.z, bv.w};
#pragma unroll
            for (int i = 0; i < 4; i++)
#pragma unroll
                for (int j = 0; j < 4; j++) acc[i][j] += a[i] * b[j];
        }
        __syncthreads();
    }
    int gn = j0 + tx * 4;
    if (gn < Nc) {
        float4 bb = *(const float4*)&bias[gn];
#pragma unroll
        for (int i = 0; i < 4; i++) {
            int gm = i0 + ty * 4 + i;
            if (gm < M) {
                float4 v;
                v.x = acc[i][0] + bb.x; v.y = acc[i][1] + bb.y;
                v.z = acc[i][2] + bb.z; v.w = acc[i][3] + bb.w;
                *(float4*)&C[(size_t)gm * Nc + gn] = v;
            }
        }
    }
}

// ---------------- fused GATv2 score + softmax + aggregate (per-node block) ----------------
template <int H, int C, int BLOCK>
__global__ void gat_aggregate_kernel(const float* __restrict__ xl, const float* __restrict__ xr,
                                     const float* __restrict__ att, const float* __restrict__ bo,
                                     const int* __restrict__ off, const int* __restrict__ adj,
                                     float* __restrict__ out, int applyElu) {
    constexpr int HC = H * C;
    constexpr int CHUNK = 512;
    constexpr int NW = BLOCK / 32;
    __shared__ float s_xr[HC];
    __shared__ float s_att[HC];
    __shared__ int   s_src[CHUNK];
    __shared__ float s_sc[CHUNK * H];
    __shared__ float s_m[H], s_d[H], s_r[H];

    int node = blockIdx.x;
    int tid = threadIdx.x;
    int lane = tid & 31, wid = tid >> 5;
    int beg = off[node], end = off[node + 1];

    for (int t = tid; t < HC; t += BLOCK) {
        s_xr[t] = xr[(size_t)node * HC + t];
        s_att[t] = att[t];
    }
    if (tid < H) { s_m[tid] = -1e30f; s_d[tid] = 0.f; }
    float acc = 0.f;
    __syncthreads();

    for (int c0 = beg; c0 < end; c0 += CHUNK) {
        int n = min(CHUNK, end - c0);
        for (int t = tid; t < n; t += BLOCK) s_src[t] = adj[c0 + t];
        __syncthreads();

        // warp-per-edge scores
        for (int e = wid; e < n; e += NW) {
            const float* xle = xl + (size_t)s_src[e] * HC;
#pragma unroll
            for (int h = 0; h < H; h++) {
                float p = 0.f;
#pragma unroll
                for (int c = lane; c < C; c += 32) {
                    float v = xle[h * C + c] + s_xr[h * C + c];
                    v = v > 0.f ? v : 0.2f * v;
                    p += v * s_att[h * C + c];
                }
#pragma unroll
                for (int o = 16; o > 0; o >>= 1) p += __shfl_xor_sync(0xffffffffu, p, o);
                if (lane == 0) s_sc[e * H + h] = p;
            }
        }
        __syncthreads();

        // online softmax stats per head (warp h)
        if (wid < H) {
            int h = wid;
            float mloc = -1e30f;
            for (int e = lane; e < n; e += 32) mloc = fmaxf(mloc, s_sc[e * H + h]);
#pragma unroll
            for (int o = 16; o > 0; o >>= 1) mloc = fmaxf(mloc, __shfl_xor_sync(0xffffffffu, mloc, o));
            float mold = s_m[h];
            float mnew = fmaxf(mold, mloc);
            float r = __expf(mold - mnew);  // 0 on first chunk
            float sum = 0.f;
            for (int e = lane; e < n; e += 32) {
                float w = __expf(s_sc[e * H + h] - mnew);
                s_sc[e * H + h] = w;
                sum += w;
            }
#pragma unroll
            for (int o = 16; o > 0; o >>= 1) sum += __shfl_xor_sync(0xffffffffu, sum, o);
            if (lane == 0) { s_m[h] = mnew; s_d[h] = s_d[h] * r + sum; s_r[h] = r; }
        }
        __syncthreads();

        // weighted accumulation (channel per thread), deterministic order
        if (tid < HC) {
            int h = tid / C;
            acc *= s_r[h];
            for (int e = 0; e < n; e++)
                acc += s_sc[e * H + h] * xl[(size_t)s_src[e] * HC + tid];
        }
        __syncthreads();
    }

    if (tid < HC) {
        int h = tid / C;
        float o = acc / (s_d[h] + 1e-16f) + bo[tid];
        if (applyElu) o = o > 0.f ? o : expm1f(o);
        out[(size_t)node * HC + tid] = o;
    }
}

// ---------------- reparameterize ----------------
__global__ void z_kernel(const float* __restrict__ mu, const float* __restrict__ lv,
                         const float* __restrict__ eps, float* __restrict__ z) {
    int i = blockIdx.x * blockDim.x + threadIdx.x;
    if (i < NN * 32) z[i] = mu[i] + eps[i] * __expf(0.5f * lv[i]);
}

// ---------------- adj = z @ z^T ----------------
__global__ void zzt_kernel(const float* __restrict__ z, float* __restrict__ out) {
    __shared__ float Zi[64][33];
    __shared__ float Zj[64][33];
    int tid = threadIdx.x;
    int tx = tid & 15, ty = tid >> 4;
    int i0 = blockIdx.y * 64, j0 = blockIdx.x * 64;
#pragma unroll
    for (int l = 0; l < 8; l++) {
        int lin = tid + l * 256;
        int r = lin >> 5, k = lin & 31;
        int gi = i0 + r, gj = j0 + r;
        Zi[r][k] = (gi < NN) ? z[(size_t)gi * 32 + k] : 0.f;
        Zj[r][k] = (gj < NN) ? z[(size_t)gj * 32 + k] : 0.f;
    }
    __syncthreads();
    float acc[4][4] = {};
#pragma unroll
    for (int k = 0; k < 32; k++) {
        float a[4], b[4];
#pragma unroll
        for (int i = 0; i < 4; i++) a[i] = Zi[ty * 4 + i][k];
#pragma unroll
        for (int j = 0; j < 4; j++) b[j] = Zj[tx * 4 + j][k];
#pragma unroll
        for (int i = 0; i < 4; i++)
#pragma unroll
            for (int j = 0; j < 4; j++) acc[i][j] += a[i] * b[j];
    }
    int gj = j0 + tx * 4;
    if (gj < NN) {
#pragma unroll
        for (int i = 0; i < 4; i++) {
            int gi = i0 + ty * 4 + i;
            if (gi < NN) {
                float4 v = {acc[i][0], acc[i][1], acc[i][2], acc[i][3]};
                *(float4*)&out[(size_t)gi * NN + gj] = v;
            }
        }
    }
}

// ---------------- launch ----------------
extern "C" void kernel_launch(void* const* d_in, const int* in_sizes, int n_in,
                              void* d_out, int out_size) {
    const float* x   = (const float*)d_in[0];
    const int*   ei  = (const int*)d_in[1];
    const float* eps = (const float*)d_in[2];

    const float* Wl0 = (const float*)d_in[3];
    const float* bl0 = (const float*)d_in[4];
    const float* Wr0 = (const float*)d_in[5];
    const float* br0 = (const float*)d_in[6];
    const float* at0 = (const float*)d_in[7];
    const float* bo0 = (const float*)d_in[8];

    const float* Wl1 = (const float*)d_in[9];
    const float* bl1 = (const float*)d_in[10];
    const float* Wr1 = (const float*)d_in[11];
    const float* br1 = (const float*)d_in[12];
    const float* at1 = (const float*)d_in[13];
    const float* bo1 = (const float*)d_in[14];

    const float* Wlm = (const float*)d_in[15];
    const float* blm = (const float*)d_in[16];
    const float* Wrm = (const float*)d_in[17];
    const float* brm = (const float*)d_in[18];
    const float* atm = (const float*)d_in[19];
    const float* bom = (const float*)d_in[20];

    const float* Wlv = (const float*)d_in[21];
    const float* blv = (const float*)d_in[22];
    const float* Wrv = (const float*)d_in[23];
    const float* brv = (const float*)d_in[24];
    const float* atv = (const float*)d_in[25];
    const float* bov = (const float*)d_in[26];

    float* out    = (float*)d_out;
    float* out_mu = out + (size_t)NN * NN;
    float* out_lv = out_mu + (size_t)NN * 32;

    void *pxl, *pxr, *ph0, *ph1, *pz, *pdeg, *pcur, *poff, *padj;
    cudaGetSymbolAddress(&pxl, g_xl);
    cudaGetSymbolAddress(&pxr, g_xr);
    cudaGetSymbolAddress(&ph0, g_h0);
    cudaGetSymbolAddress(&ph1, g_h1);
    cudaGetSymbolAddress(&pz, g_z);
    cudaGetSymbolAddress(&pdeg, g_deg);
    cudaGetSymbolAddress(&pcur, g_cur);
    cudaGetSymbolAddress(&poff, g_off);
    cudaGetSymbolAddress(&padj, g_adj);

    float* xl = (float*)pxl; float* xr = (float*)pxr;
    float* h0 = (float*)ph0; float* h1 = (float*)ph1;
    float* zp = (float*)pz;
    int* deg = (int*)pdeg; int* cur = (int*)pcur;
    int* off = (int*)poff; int* adj = (int*)padj;

    // CSR build (deterministic after per-node sort)
    zero_kernel<<<(NN + 255) / 256, 256>>>(deg, cur, NN);
    count_kernel<<<(ET + 255) / 256, 256>>>(ei, deg);
    scan_kernel<<<1, 1024>>>(deg, off);
    scatter_kernel<<<(ET + 255) / 256, 256>>>(ei, off, cur, adj);
    sort_kernel<<<(NN + 127) / 128, 128>>>(off, adj);

    dim3 gBig((256 + 63) / 64, (NN + 63) / 64);
    dim3 gSml((32 + 63) / 64, (NN + 63) / 64);

    // layer 0
    gemm_bias_kernel<<<gBig, 256>>>(x, Wl0, bl0, xl, NN, DIN, 256);
    gemm_bias_kernel<<<gBig, 256>>>(x, Wr0, br0, xr, NN, DIN, 256);
    gat_aggregate_kernel<4, 64, 256><<<NN, 256>>>(xl, xr, at0, bo0, off, adj, h0, 1);

    // layer 1
    gemm_bias_kernel<<<gBig, 256>>>(h0, Wl1, bl1, xl, NN, 256, 256);
    gemm_bias_kernel<<<gBig, 256>>>(h0, Wr1, br1, xr, NN, 256, 256);
    gat_aggregate_kernel<4, 64, 256><<<NN, 256>>>(xl, xr, at1, bo1, off, adj, h1, 1);

    // mu head
    gemm_bias_kernel<<<gSml, 256>>>(h1, Wlm, blm, xl, NN, 256, 32);
    gemm_bias_kernel<<<gSml, 256>>>(h1, Wrm, brm, xr, NN, 256, 32);
    gat_aggregate_kernel<1, 32, 128><<<NN, 128>>>(xl, xr, atm, bom, off, adj, out_mu, 0);

    // log_var head
    gemm_bias_kernel<<<gSml, 256>>>(h1, Wlv, blv, xl, NN, 256, 32);
    gemm_bias_kernel<<<gSml, 256>>>(h1, Wrv, brv, xr, NN, 256, 32);
    gat_aggregate_kernel<1, 32, 128><<<NN, 128>>>(xl, xr, atv, bov, off, adj, out_lv, 0);

    // reparameterize + dense decode
    z_kernel<<<(NN * 32 + 255) / 256, 256>>>(out_mu, out_lv, eps, zp);
    zzt_kernel<<<dim3((NN + 63) / 64, (NN + 63) / 64), 256>>>(zp, out);
}